// round 3
// baseline (speedup 1.0000x reference)
#include <cuda_runtime.h>

// Reference shapes: N=16384, MAXL=2048, C=4096, B=N/8=2048.
// Dims are derived from in_sizes at launch; these are capacity bounds only.
#define MAX_B    16384
#define SMEM_C   4096      // floats staged per row (16 KB)

// Scratch for per-row products (device allocation is forbidden in kernel_launch)
__device__ float g_rowprod[MAX_B];

__global__ __launch_bounds__(256) void row_prod_kernel(
    const float* __restrict__ x,
    const long long* __restrict__ y,
    const long long* __restrict__ lengths,
    int maxL, int C)
{
    __shared__ float sx[SMEM_C];
    const int b   = blockIdx.x;
    const int tid = threadIdx.x;
    const int L   = (int)lengths[b];

    // Coalesced float4 load of x[b, :] into shared memory.
    const float4* __restrict__ xrow4 = (const float4*)(x + (size_t)b * C);
    float4* s4 = (float4*)sx;
    const int nvec = C >> 2;
    for (int i = tid; i < nvec; i += 256)
        s4[i] = xrow4[i];
    __syncthreads();

    // Each thread multiplies its strided subset of (1 - x[b, y[b,j]]).
    // y vectorized as longlong2: pair p covers j = 2p, 2p+1.
    float acc = 1.0f;
    const longlong2* __restrict__ yrow2 =
        (const longlong2*)(y + (size_t)b * maxL);
    const int npairs_full = L >> 1;
    for (int p = tid; p < npairs_full; p += 256) {
        longlong2 v = __ldg(yrow2 + p);
        acc *= (1.0f - sx[(int)v.x]);
        acc *= (1.0f - sx[(int)v.y]);
    }
    // Odd tail (element L-1): safe because L <= maxL-1, so element L is in-row.
    if ((L & 1) && tid == 0) {
        longlong2 v = __ldg(yrow2 + (L >> 1));
        acc *= (1.0f - sx[(int)v.x]);
    }

    // Warp product reduction
    #pragma unroll
    for (int off = 16; off > 0; off >>= 1)
        acc *= __shfl_xor_sync(0xffffffffu, acc, off);

    __shared__ float wprod[8];
    if ((tid & 31) == 0) wprod[tid >> 5] = acc;
    __syncthreads();

    if (tid == 0) {
        float prod = wprod[0];
        #pragma unroll
        for (int w = 1; w < 8; w++) prod *= wprod[w];
        g_rowprod[b] = prod;
    }
}

__global__ __launch_bounds__(256) void reduce_kernel(float* __restrict__ out, int B)
{
    const int tid = threadIdx.x;
    float acc = 0.0f;
    for (int i = tid; i < B; i += 256)
        acc += 1.0f - g_rowprod[i];

    #pragma unroll
    for (int off = 16; off > 0; off >>= 1)
        acc += __shfl_xor_sync(0xffffffffu, acc, off);

    __shared__ float wsum[8];
    if ((tid & 31) == 0) wsum[tid >> 5] = acc;
    __syncthreads();

    if (tid == 0) {
        float t = 0.0f;
        #pragma unroll
        for (int w = 0; w < 8; w++) t += wsum[w];
        out[0] = t;
    }
}

extern "C" void kernel_launch(void* const* d_in, const int* in_sizes, int n_in,
                              void* d_out, int out_size)
{
    const float*     x       = (const float*)d_in[0];
    const long long* y       = (const long long*)d_in[1];
    const long long* lengths = (const long long*)d_in[2];
    float* out = (float*)d_out;

    const int N    = in_sizes[2];                 // lengths has N elements
    const int B    = N / 8;
    const int maxL = in_sizes[1] / N;             // y is N x MAXL
    const int C    = in_sizes[0] / N;             // x is N x C

    row_prod_kernel<<<B, 256>>>(x, y, lengths, maxL, C);
    reduce_kernel<<<1, 256>>>(out, B);
}

// round 4
// speedup vs baseline: 1.0753x; 1.0753x over previous
#include <cuda_runtime.h>

#define MAX_B 16384

// Scratch (device allocation is forbidden in kernel_launch)
__device__ float g_rowprod[MAX_B];
__device__ unsigned int g_done = 0;

__global__ __launch_bounds__(256) void fused_loss_kernel(
    const float* __restrict__ x,
    const long long* __restrict__ y,
    const long long* __restrict__ lengths,
    float* __restrict__ out,
    int maxL, int C, int B)
{
    const int b   = blockIdx.x;
    const int tid = threadIdx.x;
    const int L   = (int)lengths[b];

    const float* __restrict__ xrow = x + (size_t)b * C;
    const longlong2* __restrict__ yrow2 = (const longlong2*)(y + (size_t)b * maxL);

    __shared__ float swarp[8];

    // Block-replicated running product. Factors are in (0,1], so the product is
    // non-increasing: once it drops below EPS the row's final product is < EPS,
    // and stopping is exact to within EPS per row (tolerance is ~2 absolute).
    const float EPS = 1e-20f;
    float total = 1.0f;
    const int npairs = L >> 1;

    for (int pbase = 0; pbase < npairs; pbase += 256) {
        float acc = 1.0f;
        const int p = pbase + tid;
        if (p < npairs) {
            longlong2 v = __ldg(yrow2 + p);
            float a = __ldg(xrow + (int)v.x);
            float c = __ldg(xrow + (int)v.y);
            acc = (1.0f - a) * (1.0f - c);
        }
        // Block product reduction (replicated result).
        #pragma unroll
        for (int off = 16; off > 0; off >>= 1)
            acc *= __shfl_xor_sync(0xffffffffu, acc, off);
        if ((tid & 31) == 0) swarp[tid >> 5] = acc;
        __syncthreads();
        float chunk = swarp[0] * swarp[1] * swarp[2] * swarp[3]
                    * swarp[4] * swarp[5] * swarp[6] * swarp[7];
        total *= chunk;
        __syncthreads();            // protect swarp reuse
        if (total < EPS) break;     // uniform: total is block-replicated
    }

    // Odd tail element (j = L-1). Element L is in-row since L <= maxL-1.
    if (tid == 0) {
        if ((L & 1) && total >= EPS) {
            longlong2 v = __ldg(yrow2 + npairs);
            total *= (1.0f - __ldg(xrow + (int)v.x));
        }
        g_rowprod[b] = total;
    }

    // Last-block-done final reduction (deterministic: fixed read order).
    __threadfence();
    __shared__ unsigned int sdone;
    if (tid == 0) sdone = atomicAdd(&g_done, 1u);
    __syncthreads();

    if (sdone == (unsigned int)(B - 1)) {
        float s = 0.0f;
        for (int i = tid; i < B; i += 256)
            s += 1.0f - g_rowprod[i];
        #pragma unroll
        for (int off = 16; off > 0; off >>= 1)
            s += __shfl_xor_sync(0xffffffffu, s, off);
        if ((tid & 31) == 0) swarp[tid >> 5] = s;
        __syncthreads();
        if (tid == 0) {
            float t = swarp[0] + swarp[1] + swarp[2] + swarp[3]
                    + swarp[4] + swarp[5] + swarp[6] + swarp[7];
            out[0] = t;
            g_done = 0;             // reset for next graph replay
        }
    }
}

extern "C" void kernel_launch(void* const* d_in, const int* in_sizes, int n_in,
                              void* d_out, int out_size)
{
    const float*     x       = (const float*)d_in[0];
    const long long* y       = (const long long*)d_in[1];
    const long long* lengths = (const long long*)d_in[2];
    float* out = (float*)d_out;

    const int N    = in_sizes[2];       // lengths has N elements
    const int B    = N / 8;
    const int maxL = in_sizes[1] / N;   // y is N x MAXL
    const int C    = in_sizes[0] / N;   // x is N x C

    fused_loss_kernel<<<B, 256>>>(x, y, lengths, out, maxL, C, B);
}

// round 5
// speedup vs baseline: 1.6109x; 1.4981x over previous
#include <cuda_runtime.h>

#define MAX_B 16384

// Scratch (device allocation is forbidden in kernel_launch)
__device__ float g_rowprod[MAX_B];
__device__ unsigned int g_done = 0;

// 8 warps per block, one row per warp.
__global__ __launch_bounds__(256) void fused_loss_kernel(
    const float* __restrict__ x,
    const long long* __restrict__ y,
    const long long* __restrict__ lengths,
    float* __restrict__ out,
    int maxL, int C, int B)
{
    const int tid  = threadIdx.x;
    const int lane = tid & 31;
    const int wid  = tid >> 5;
    const int b    = blockIdx.x * 8 + wid;

    if (b < B) {
        const int L = (int)lengths[b];
        const float* __restrict__ xrow = x + (size_t)b * C;
        const longlong2* __restrict__ yrow2 = (const longlong2*)(y + (size_t)b * maxL);

        // Early termination: factors are in (0,1], so the running product is
        // non-increasing. Once warp product < EPS the true row product is < EPS;
        // stopping adds < EPS absolute error per row (loss is O(1e3), eps free).
        const float EPS = 1e-12f;
        float total = 1.0f;
        const int npairs = L >> 1;

        for (int pbase = 0; pbase < npairs; pbase += 32) {
            const int p = pbase + lane;
            float acc = 1.0f;
            if (p < npairs) {
                longlong2 v = __ldg(yrow2 + p);
                float a = __ldg(xrow + (int)v.x);
                float c = __ldg(xrow + (int)v.y);
                acc = (1.0f - a) * (1.0f - c);
            }
            // Warp product reduction (result replicated to all lanes).
            #pragma unroll
            for (int off = 16; off > 0; off >>= 1)
                acc *= __shfl_xor_sync(0xffffffffu, acc, off);
            total *= acc;
            if (total < EPS) break;      // warp-uniform
        }

        if (lane == 0) {
            // Odd tail (j = L-1): element L is in-row since L <= maxL-1.
            if ((L & 1) && total >= EPS) {
                longlong2 v = __ldg(yrow2 + npairs);
                total *= (1.0f - __ldg(xrow + (int)v.x));
            }
            g_rowprod[b] = total;
        }
    }

    // Last-block-done final reduction (deterministic: fixed read order).
    __threadfence();
    __syncthreads();
    __shared__ unsigned int sdone;
    if (tid == 0) sdone = atomicAdd(&g_done, 1u);
    __syncthreads();

    const unsigned int nblocks = (unsigned int)((B + 7) / 8);
    if (sdone == nblocks - 1) {
        __shared__ float swarp[8];
        float s = 0.0f;
        for (int i = tid; i < B; i += 256)
            s += 1.0f - g_rowprod[i];
        #pragma unroll
        for (int off = 16; off > 0; off >>= 1)
            s += __shfl_xor_sync(0xffffffffu, s, off);
        if (lane == 0) swarp[wid] = s;
        __syncthreads();
        if (tid == 0) {
            float t = swarp[0] + swarp[1] + swarp[2] + swarp[3]
                    + swarp[4] + swarp[5] + swarp[6] + swarp[7];
            out[0] = t;
            g_done = 0;                 // reset for next graph replay
        }
    }
}

extern "C" void kernel_launch(void* const* d_in, const int* in_sizes, int n_in,
                              void* d_out, int out_size)
{
    const float*     x       = (const float*)d_in[0];
    const long long* y       = (const long long*)d_in[1];
    const long long* lengths = (const long long*)d_in[2];
    float* out = (float*)d_out;

    const int N    = in_sizes[2];       // lengths has N elements
    const int B    = N / 8;
    const int maxL = in_sizes[1] / N;   // y is N x MAXL
    const int C    = in_sizes[0] / N;   // x is N x C

    fused_loss_kernel<<<(B + 7) / 8, 256>>>(x, y, lengths, out, maxL, C, B);
}